// round 7
// baseline (speedup 1.0000x reference)
#include <cuda_runtime.h>
#include <cuda_bf16.h>
#include <cstdint>

// 2-layer LSTM scan, B=1024, H=64, S=512, warp-level HMMA bf16 split-precision.
// R6: 2 phases/step (was 4). Phase A: MMA2(t) + MMA1(t+1) (MMA1 needs only
// h1(t)); Phase B: act2(t) + act1(t+1). 2 barriers/step.
// 128 CTAs x 512 threads; warp w owns gate rows [16w,16w+16) for both layers.
// Weights persistent in regs as bf16 hi/lo A-fragments; 3-pass split precision.

#define HID 64
#define NB  8
#define TPB 512
#define BATCH 1024
#define SEQ 512
#define NCTA (BATCH/NB)      // 128
#define HSW 68               // hs row stride in words
#define GSTR 264             // gate buffer row stride (floats)

__device__ __forceinline__ uint32_t packbf(float a, float b) {
    __nv_bfloat162 v = __floats2bfloat162_rn(a, b);
    return *(uint32_t*)&v;
}
__device__ __forceinline__ void mma16816(float* d, const uint32_t* a,
                                         uint32_t b0, uint32_t b1) {
    asm("mma.sync.aligned.m16n8k16.row.col.f32.bf16.bf16.f32 "
        "{%0,%1,%2,%3}, {%4,%5,%6,%7}, {%8,%9}, {%0,%1,%2,%3};"
        : "+f"(d[0]), "+f"(d[1]), "+f"(d[2]), "+f"(d[3])
        : "r"(a[0]), "r"(a[1]), "r"(a[2]), "r"(a[3]), "r"(b0), "r"(b1));
}
__device__ __forceinline__ float fsigmoid(float x) {
    return __fdividef(1.0f, 1.0f + __expf(-x));
}
__device__ __forceinline__ float ftanh(float x) {
    float xx = fminf(fmaxf(x, -15.0f), 15.0f);
    float e = __expf(2.0f * xx);
    return __fdividef(e - 1.0f, e + 1.0f);
}

__global__ __launch_bounds__(TPB, 1)
void lstm_kernel(const float* __restrict__ input,
                 const float* __restrict__ W_ih1, const float* __restrict__ W_hh1,
                 const float* __restrict__ b_ih1, const float* __restrict__ b_hh1,
                 const float* __restrict__ W_ih2, const float* __restrict__ W_hh2,
                 const float* __restrict__ b_ih2, const float* __restrict__ b_hh2,
                 const float* __restrict__ W_lin, const float* __restrict__ b_lin,
                 float* __restrict__ out)
{
    __shared__ uint32_t hs[2][NB][HSW];   // bf16 pairs; k 0..63=h1, 64..127=h2
    __shared__ float g1sh[NB][GSTR];      // layer-1 gates for step t+1
    __shared__ float g2sh[NB][GSTR];      // layer-2 gates for step t
    __shared__ float wxs[256], b1s[256], b2s[256], wls[HID];
    __shared__ float reds[16];
    __shared__ float blin;

    const int tid  = threadIdx.x;
    const int w    = tid >> 5, lane = tid & 31;
    const int g    = lane >> 2, tq = lane & 3;
    const int R    = 16 * w + g;
    const int b0   = blockIdx.x * NB;
    const int ab   = tid >> 6;            // act batch (0..7)
    const int aj   = tid & 63;            // act hidden index

    // ---- Persistent A-fragments (hi/lo bf16) ----
    uint32_t wa1[2][4][4];
    uint32_t wa2[2][8][4];
    #pragma unroll
    for (int kt = 0; kt < 4; kt++) {
        #pragma unroll
        for (int r = 0; r < 4; r++) {
            int row = R + ((r & 1) ? 8 : 0);
            int cb  = kt * 16 + ((r >= 2) ? 8 : 0) + 2 * tq;
            float v0 = W_hh1[row * HID + cb], v1 = W_hh1[row * HID + cb + 1];
            float h0 = __bfloat162float(__float2bfloat16(v0));
            float h1 = __bfloat162float(__float2bfloat16(v1));
            wa1[0][kt][r] = packbf(h0, h1);
            wa1[1][kt][r] = packbf(v0 - h0, v1 - h1);
        }
    }
    #pragma unroll
    for (int kt = 0; kt < 8; kt++) {
        #pragma unroll
        for (int r = 0; r < 4; r++) {
            int row = R + ((r & 1) ? 8 : 0);
            int cb  = kt * 16 + ((r >= 2) ? 8 : 0) + 2 * tq;
            float v0 = (cb < 64) ? W_ih2[row * HID + cb]
                                 : W_hh2[row * HID + cb - 64];
            float v1 = (cb + 1 < 64) ? W_ih2[row * HID + cb + 1]
                                     : W_hh2[row * HID + cb + 1 - 64];
            float h0 = __bfloat162float(__float2bfloat16(v0));
            float h1 = __bfloat162float(__float2bfloat16(v1));
            wa2[0][kt][r] = packbf(h0, h1);
            wa2[1][kt][r] = packbf(v0 - h0, v1 - h1);
        }
    }

    // ---- Init SMEM ----
    for (int i = tid; i < 2 * NB * HSW; i += TPB) ((uint32_t*)hs)[i] = 0;
    for (int i = tid; i < 256; i += TPB) {
        wxs[i] = W_ih1[i];
        b1s[i] = b_ih1[i] + b_hh1[i];
        b2s[i] = b_ih2[i] + b_hh2[i];
    }
    if (tid < HID) wls[tid] = W_lin[tid];
    if (tid == 0) blin = b_lin[0];
    __syncthreads();

    float c1 = 0.f, c2 = 0.f;

    // ---- Peel act1(0): h1(-1)=0 so gates = wx*x(0) + bias ----
    {
        const float x0 = input[(b0 + ab) * SEQ + 0];
        float gI = fmaf(wxs[aj],       x0, b1s[aj]);
        float gF = fmaf(wxs[64 + aj],  x0, b1s[64 + aj]);
        float gG = fmaf(wxs[128 + aj], x0, b1s[128 + aj]);
        float gO = fmaf(wxs[192 + aj], x0, b1s[192 + aj]);
        float cn = fsigmoid(gF) * c1 + fsigmoid(gI) * ftanh(gG);
        c1 = cn;
        float h = fsigmoid(gO) * ftanh(cn);
        __nv_bfloat16 hi = __float2bfloat16(h);
        ((__nv_bfloat16*)&hs[0][ab][0])[aj] = hi;
        ((__nv_bfloat16*)&hs[1][ab][0])[aj] =
            __float2bfloat16(h - __bfloat162float(hi));
    }
    __syncthreads();

    for (int ts = 0; ts < SEQ; ts++) {
        // x(t+1) prefetch for act1(t+1) in phase B
        const float xnext = (ts + 1 < SEQ)
            ? input[(b0 + ab) * SEQ + ts + 1] : 0.f;

        // ===== Phase A: out(t-1) + MMA2(t) + MMA1(t+1) =====
        if (ts > 0 && tid < NB)
            out[(b0 + tid) * SEQ + (ts - 1)] = reds[2 * tid] + reds[2 * tid + 1] + blin;

        {
            // --- MMA2(t): gates2 = [W_ih2|W_hh2] @ [h1(t); h2(t-1)] ---
            float d[4] = {0.f, 0.f, 0.f, 0.f};
            float e[4] = {0.f, 0.f, 0.f, 0.f};
            uint32_t bh0c[4], bh1c[4], bl0c[4], bl1c[4];  // h1-half frags (reused)
            #pragma unroll
            for (int kt = 0; kt < 8; kt++) {
                uint32_t bh0 = hs[0][g][kt * 8 + tq];
                uint32_t bh1 = hs[0][g][kt * 8 + 4 + tq];
                uint32_t bl0 = hs[1][g][kt * 8 + tq];
                uint32_t bl1 = hs[1][g][kt * 8 + 4 + tq];
                if (kt < 4) { bh0c[kt] = bh0; bh1c[kt] = bh1;
                              bl0c[kt] = bl0; bl1c[kt] = bl1; }
                mma16816(d, wa2[0][kt], bh0, bh1);
                mma16816(e, wa2[1][kt], bh0, bh1);
                mma16816(e, wa2[0][kt], bl0, bl1);
            }
            g2sh[2 * tq    ][R    ] = d[0] + e[0];
            g2sh[2 * tq + 1][R    ] = d[1] + e[1];
            g2sh[2 * tq    ][R + 8] = d[2] + e[2];
            g2sh[2 * tq + 1][R + 8] = d[3] + e[3];

            // --- MMA1(t+1): gates1 = W_hh1 @ h1(t) (same B frags as kt<4) ---
            if (ts + 1 < SEQ) {
                float d1[4] = {0.f, 0.f, 0.f, 0.f};
                float e1[4] = {0.f, 0.f, 0.f, 0.f};
                #pragma unroll
                for (int kt = 0; kt < 4; kt++) {
                    mma16816(d1, wa1[0][kt], bh0c[kt], bh1c[kt]);
                    mma16816(e1, wa1[1][kt], bh0c[kt], bh1c[kt]);
                    mma16816(e1, wa1[0][kt], bl0c[kt], bl1c[kt]);
                }
                g1sh[2 * tq    ][R    ] = d1[0] + e1[0];
                g1sh[2 * tq + 1][R    ] = d1[1] + e1[1];
                g1sh[2 * tq    ][R + 8] = d1[2] + e1[2];
                g1sh[2 * tq + 1][R + 8] = d1[3] + e1[3];
            }
        }
        __syncthreads();

        // ===== Phase B: act2(t) + act1(t+1) =====
        {   // act2(t)
            float gI = g2sh[ab][aj]       + b2s[aj];
            float gF = g2sh[ab][64 + aj]  + b2s[64 + aj];
            float gG = g2sh[ab][128 + aj] + b2s[128 + aj];
            float gO = g2sh[ab][192 + aj] + b2s[192 + aj];
            float cn = fsigmoid(gF) * c2 + fsigmoid(gI) * ftanh(gG);
            c2 = cn;
            float h = fsigmoid(gO) * ftanh(cn);
            __nv_bfloat16 hi = __float2bfloat16(h);
            ((__nv_bfloat16*)&hs[0][ab][0])[64 + aj] = hi;
            ((__nv_bfloat16*)&hs[1][ab][0])[64 + aj] =
                __float2bfloat16(h - __bfloat162float(hi));
            float vout = wls[aj] * h;
            #pragma unroll
            for (int off = 16; off; off >>= 1)
                vout += __shfl_down_sync(0xFFFFFFFFu, vout, off);
            if (lane == 0) reds[w] = vout;
        }
        if (ts + 1 < SEQ) {   // act1(t+1)
            float gI = g1sh[ab][aj]       + fmaf(wxs[aj],       xnext, b1s[aj]);
            float gF = g1sh[ab][64 + aj]  + fmaf(wxs[64 + aj],  xnext, b1s[64 + aj]);
            float gG = g1sh[ab][128 + aj] + fmaf(wxs[128 + aj], xnext, b1s[128 + aj]);
            float gO = g1sh[ab][192 + aj] + fmaf(wxs[192 + aj], xnext, b1s[192 + aj]);
            float cn = fsigmoid(gF) * c1 + fsigmoid(gI) * ftanh(gG);
            c1 = cn;
            float h = fsigmoid(gO) * ftanh(cn);
            __nv_bfloat16 hi = __float2bfloat16(h);
            ((__nv_bfloat16*)&hs[0][ab][0])[aj] = hi;
            ((__nv_bfloat16*)&hs[1][ab][0])[aj] =
                __float2bfloat16(h - __bfloat162float(hi));
        }
        __syncthreads();
    }

    // Final output (t = SEQ-1)
    if (tid < NB)
        out[(b0 + tid) * SEQ + (SEQ - 1)] = reds[2 * tid] + reds[2 * tid + 1] + blin;
}

extern "C" void kernel_launch(void* const* d_in, const int* in_sizes, int n_in,
                              void* d_out, int out_size) {
    (void)in_sizes; (void)n_in; (void)out_size;
    const float* input = (const float*)d_in[0];
    const float* W_ih1 = (const float*)d_in[1];
    const float* W_hh1 = (const float*)d_in[2];
    const float* b_ih1 = (const float*)d_in[3];
    const float* b_hh1 = (const float*)d_in[4];
    const float* W_ih2 = (const float*)d_in[5];
    const float* W_hh2 = (const float*)d_in[6];
    const float* b_ih2 = (const float*)d_in[7];
    const float* b_hh2 = (const float*)d_in[8];
    const float* W_lin = (const float*)d_in[9];
    const float* b_lin = (const float*)d_in[10];
    float* out = (float*)d_out;

    lstm_kernel<<<NCTA, TPB>>>(input, W_ih1, W_hh1, b_ih1, b_hh1,
                               W_ih2, W_hh2, b_ih2, b_hh2,
                               W_lin, b_lin, out);
}

// round 8
// speedup vs baseline: 1.0741x; 1.0741x over previous
#include <cuda_runtime.h>
#include <cuda_bf16.h>
#include <cstdint>

// 2-layer LSTM scan, B=1024, H=64, S=512, warp-level HMMA bf16 split-precision.
// R7: 2 phases/step, spill-free. Phase A: MMA1(t+1) then MMA2(t) — no frag
// caching, one accumulator set live at a time. Phase B: act2(t) + act1(t+1).
// 128 CTAs x 512 threads; warp w owns gate rows [16w,16w+16) for both layers.
// Weights persistent in regs as bf16 hi/lo A-fragments; 3-pass split precision.

#define HID 64
#define NB  8
#define TPB 512
#define BATCH 1024
#define SEQ 512
#define NCTA (BATCH/NB)      // 128
#define HSW 68               // hs row stride in words
#define GSTR 264             // gate buffer row stride (floats)

__device__ __forceinline__ uint32_t packbf(float a, float b) {
    __nv_bfloat162 v = __floats2bfloat162_rn(a, b);
    return *(uint32_t*)&v;
}
__device__ __forceinline__ void mma16816(float* d, const uint32_t* a,
                                         uint32_t b0, uint32_t b1) {
    asm("mma.sync.aligned.m16n8k16.row.col.f32.bf16.bf16.f32 "
        "{%0,%1,%2,%3}, {%4,%5,%6,%7}, {%8,%9}, {%0,%1,%2,%3};"
        : "+f"(d[0]), "+f"(d[1]), "+f"(d[2]), "+f"(d[3])
        : "r"(a[0]), "r"(a[1]), "r"(a[2]), "r"(a[3]), "r"(b0), "r"(b1));
}
__device__ __forceinline__ float fsigmoid(float x) {
    return __fdividef(1.0f, 1.0f + __expf(-x));
}
__device__ __forceinline__ float ftanh(float x) {
    float xx = fminf(fmaxf(x, -15.0f), 15.0f);
    float e = __expf(2.0f * xx);
    return __fdividef(e - 1.0f, e + 1.0f);
}

__global__ __launch_bounds__(TPB, 1)
void lstm_kernel(const float* __restrict__ input,
                 const float* __restrict__ W_ih1, const float* __restrict__ W_hh1,
                 const float* __restrict__ b_ih1, const float* __restrict__ b_hh1,
                 const float* __restrict__ W_ih2, const float* __restrict__ W_hh2,
                 const float* __restrict__ b_ih2, const float* __restrict__ b_hh2,
                 const float* __restrict__ W_lin, const float* __restrict__ b_lin,
                 float* __restrict__ out)
{
    __shared__ uint32_t hs[2][NB][HSW];   // bf16 pairs; k 0..63=h1, 64..127=h2
    __shared__ float g1sh[NB][GSTR];      // layer-1 gates for step t+1
    __shared__ float g2sh[NB][GSTR];      // layer-2 gates for step t
    __shared__ float wxs[256], b1s[256], b2s[256], wls[HID];
    __shared__ float reds[16];
    __shared__ float blin;

    const int tid  = threadIdx.x;
    const int w    = tid >> 5, lane = tid & 31;
    const int g    = lane >> 2, tq = lane & 3;
    const int R    = 16 * w + g;
    const int b0   = blockIdx.x * NB;
    const int ab   = tid >> 6;            // act batch (0..7)
    const int aj   = tid & 63;            // act hidden index

    // ---- Persistent A-fragments (hi/lo bf16) ----
    uint32_t wa1[2][4][4];
    uint32_t wa2[2][8][4];
    #pragma unroll
    for (int kt = 0; kt < 4; kt++) {
        #pragma unroll
        for (int r = 0; r < 4; r++) {
            int row = R + ((r & 1) ? 8 : 0);
            int cb  = kt * 16 + ((r >= 2) ? 8 : 0) + 2 * tq;
            float v0 = W_hh1[row * HID + cb], v1 = W_hh1[row * HID + cb + 1];
            float h0 = __bfloat162float(__float2bfloat16(v0));
            float h1 = __bfloat162float(__float2bfloat16(v1));
            wa1[0][kt][r] = packbf(h0, h1);
            wa1[1][kt][r] = packbf(v0 - h0, v1 - h1);
        }
    }
    #pragma unroll
    for (int kt = 0; kt < 8; kt++) {
        #pragma unroll
        for (int r = 0; r < 4; r++) {
            int row = R + ((r & 1) ? 8 : 0);
            int cb  = kt * 16 + ((r >= 2) ? 8 : 0) + 2 * tq;
            float v0 = (cb < 64) ? W_ih2[row * HID + cb]
                                 : W_hh2[row * HID + cb - 64];
            float v1 = (cb + 1 < 64) ? W_ih2[row * HID + cb + 1]
                                     : W_hh2[row * HID + cb + 1 - 64];
            float h0 = __bfloat162float(__float2bfloat16(v0));
            float h1 = __bfloat162float(__float2bfloat16(v1));
            wa2[0][kt][r] = packbf(h0, h1);
            wa2[1][kt][r] = packbf(v0 - h0, v1 - h1);
        }
    }

    // ---- Init SMEM ----
    for (int i = tid; i < 2 * NB * HSW; i += TPB) ((uint32_t*)hs)[i] = 0;
    for (int i = tid; i < 256; i += TPB) {
        wxs[i] = W_ih1[i];
        b1s[i] = b_ih1[i] + b_hh1[i];
        b2s[i] = b_ih2[i] + b_hh2[i];
    }
    if (tid < HID) wls[tid] = W_lin[tid];
    if (tid == 0) blin = b_lin[0];
    __syncthreads();

    float c1 = 0.f, c2 = 0.f;

    // ---- Peel act1(0): h1(-1)=0 so gates = wx*x(0) + bias ----
    {
        const float x0 = input[(b0 + ab) * SEQ + 0];
        float gI = fmaf(wxs[aj],       x0, b1s[aj]);
        float gF = fmaf(wxs[64 + aj],  x0, b1s[64 + aj]);
        float gG = fmaf(wxs[128 + aj], x0, b1s[128 + aj]);
        float gO = fmaf(wxs[192 + aj], x0, b1s[192 + aj]);
        float cn = fsigmoid(gF) * c1 + fsigmoid(gI) * ftanh(gG);
        c1 = cn;
        float h = fsigmoid(gO) * ftanh(cn);
        __nv_bfloat16 hi = __float2bfloat16(h);
        ((__nv_bfloat16*)&hs[0][ab][0])[aj] = hi;
        ((__nv_bfloat16*)&hs[1][ab][0])[aj] =
            __float2bfloat16(h - __bfloat162float(hi));
    }
    __syncthreads();

    for (int ts = 0; ts < SEQ; ts++) {
        const float xnext = (ts + 1 < SEQ)
            ? input[(b0 + ab) * SEQ + ts + 1] : 0.f;

        // ===== Phase A: out(t-1), MMA1(t+1), MMA2(t) =====
        if (ts > 0 && tid < NB)
            out[(b0 + tid) * SEQ + (ts - 1)] = reds[2 * tid] + reds[2 * tid + 1] + blin;

        // --- MMA1(t+1): gates1 = W_hh1 @ h1(t) (kt 0..3) ---
        {
            float d[4] = {0.f, 0.f, 0.f, 0.f};
            float e[4] = {0.f, 0.f, 0.f, 0.f};
            #pragma unroll
            for (int kt = 0; kt < 4; kt++) {
                uint32_t bh0 = hs[0][g][kt * 8 + tq];
                uint32_t bh1 = hs[0][g][kt * 8 + 4 + tq];
                uint32_t bl0 = hs[1][g][kt * 8 + tq];
                uint32_t bl1 = hs[1][g][kt * 8 + 4 + tq];
                mma16816(d, wa1[0][kt], bh0, bh1);
                mma16816(e, wa1[1][kt], bh0, bh1);
                mma16816(e, wa1[0][kt], bl0, bl1);
            }
            g1sh[2 * tq    ][R    ] = d[0] + e[0];
            g1sh[2 * tq + 1][R    ] = d[1] + e[1];
            g1sh[2 * tq    ][R + 8] = d[2] + e[2];
            g1sh[2 * tq + 1][R + 8] = d[3] + e[3];
        }
        // --- MMA2(t): gates2 = [W_ih2|W_hh2] @ [h1(t); h2(t-1)] (kt 0..7) ---
        {
            float d[4] = {0.f, 0.f, 0.f, 0.f};
            float e[4] = {0.f, 0.f, 0.f, 0.f};
            #pragma unroll
            for (int kt = 0; kt < 8; kt++) {
                uint32_t bh0 = hs[0][g][kt * 8 + tq];
                uint32_t bh1 = hs[0][g][kt * 8 + 4 + tq];
                uint32_t bl0 = hs[1][g][kt * 8 + tq];
                uint32_t bl1 = hs[1][g][kt * 8 + 4 + tq];
                mma16816(d, wa2[0][kt], bh0, bh1);
                mma16816(e, wa2[1][kt], bh0, bh1);
                mma16816(e, wa2[0][kt], bl0, bl1);
            }
            g2sh[2 * tq    ][R    ] = d[0] + e[0];
            g2sh[2 * tq + 1][R    ] = d[1] + e[1];
            g2sh[2 * tq    ][R + 8] = d[2] + e[2];
            g2sh[2 * tq + 1][R + 8] = d[3] + e[3];
        }
        __syncthreads();

        // ===== Phase B: act2(t) + act1(t+1) =====
        {   // act2(t)
            float gI = g2sh[ab][aj]       + b2s[aj];
            float gF = g2sh[ab][64 + aj]  + b2s[64 + aj];
            float gG = g2sh[ab][128 + aj] + b2s[128 + aj];
            float gO = g2sh[ab][192 + aj] + b2s[192 + aj];
            float cn = fsigmoid(gF) * c2 + fsigmoid(gI) * ftanh(gG);
            c2 = cn;
            float h = fsigmoid(gO) * ftanh(cn);
            __nv_bfloat16 hi = __float2bfloat16(h);
            ((__nv_bfloat16*)&hs[0][ab][0])[64 + aj] = hi;
            ((__nv_bfloat16*)&hs[1][ab][0])[64 + aj] =
                __float2bfloat16(h - __bfloat162float(hi));
            float vout = wls[aj] * h;
            #pragma unroll
            for (int off = 16; off; off >>= 1)
                vout += __shfl_down_sync(0xFFFFFFFFu, vout, off);
            if (lane == 0) reds[w] = vout;
        }
        if (ts + 1 < SEQ) {   // act1(t+1)
            float gI = g1sh[ab][aj]       + fmaf(wxs[aj],       xnext, b1s[aj]);
            float gF = g1sh[ab][64 + aj]  + fmaf(wxs[64 + aj],  xnext, b1s[64 + aj]);
            float gG = g1sh[ab][128 + aj] + fmaf(wxs[128 + aj], xnext, b1s[128 + aj]);
            float gO = g1sh[ab][192 + aj] + fmaf(wxs[192 + aj], xnext, b1s[192 + aj]);
            float cn = fsigmoid(gF) * c1 + fsigmoid(gI) * ftanh(gG);
            c1 = cn;
            float h = fsigmoid(gO) * ftanh(cn);
            __nv_bfloat16 hi = __float2bfloat16(h);
            ((__nv_bfloat16*)&hs[0][ab][0])[aj] = hi;
            ((__nv_bfloat16*)&hs[1][ab][0])[aj] =
                __float2bfloat16(h - __bfloat162float(hi));
        }
        __syncthreads();
    }

    // Final output (t = SEQ-1)
    if (tid < NB)
        out[(b0 + tid) * SEQ + (SEQ - 1)] = reds[2 * tid] + reds[2 * tid + 1] + blin;
}

extern "C" void kernel_launch(void* const* d_in, const int* in_sizes, int n_in,
                              void* d_out, int out_size) {
    (void)in_sizes; (void)n_in; (void)out_size;
    const float* input = (const float*)d_in[0];
    const float* W_ih1 = (const float*)d_in[1];
    const float* W_hh1 = (const float*)d_in[2];
    const float* b_ih1 = (const float*)d_in[3];
    const float* b_hh1 = (const float*)d_in[4];
    const float* W_ih2 = (const float*)d_in[5];
    const float* W_hh2 = (const float*)d_in[6];
    const float* b_ih2 = (const float*)d_in[7];
    const float* b_hh2 = (const float*)d_in[8];
    const float* W_lin = (const float*)d_in[9];
    const float* b_lin = (const float*)d_in[10];
    float* out = (float*)d_out;

    lstm_kernel<<<NCTA, TPB>>>(input, W_ih1, W_hh1, b_ih1, b_hh1,
                               W_ih2, W_hh2, b_ih2, b_hh2,
                               W_lin, b_lin, out);
}

// round 9
// speedup vs baseline: 1.1597x; 1.0797x over previous
#include <cuda_runtime.h>
#include <cuda_bf16.h>
#include <cstdint>

// 2-layer LSTM scan, B=1024, H=64, S=512, warp-level HMMA bf16 split-precision.
// R9: spill-free + fast activations.
//  - lo-precision A-fragments live in SMEM (fragment-order, LDS.128/kt),
//    cutting persistent regs by 48 -> no spills at TPB=512.
//  - tanh.approx.f32 activations; sigmoid(x) = 0.5*tanh(x/2)+0.5.
// Structure: 2 phases/step. Phase A: MMA1(t+1) then MMA2(t). Phase B: act2(t)
// + act1(t+1). 128 CTAs x 512 threads; warp w owns gate rows [16w,16w+16).

#define HID 64
#define NB  8
#define TPB 512
#define BATCH 1024
#define SEQ 512
#define NCTA (BATCH/NB)      // 128
#define HSW 68               // hs row stride in words
#define GSTR 264             // gate buffer row stride (floats)

// ---- dynamic SMEM layout (bytes) ----
#define OFF_HS   0                         // uint32 hs[2][NB][HSW]   (4352 B)
#define OFF_G1   (OFF_HS + 4352)           // float g1[NB][GSTR]      (8448 B)
#define OFF_G2   (OFF_G1 + 8448)           // float g2[NB][GSTR]      (8448 B)
#define OFF_WX   (OFF_G2 + 8448)           // float wxs[256]
#define OFF_B1   (OFF_WX + 1024)
#define OFF_B2   (OFF_B1 + 1024)
#define OFF_WL   (OFF_B2 + 1024)           // float wls[64]
#define OFF_RED  (OFF_WL + 256)            // float reds[16]
#define OFF_BLN  (OFF_RED + 64)            // float blin (pad 16)
#define OFF_A1LO (OFF_BLN + 16)            // uint4 [16w][4kt][32ln]  (32768 B)
#define OFF_A2LO (OFF_A1LO + 32768)        // uint4 [16w][8kt][32ln]  (65536 B)
#define SMEM_TOTAL (OFF_A2LO + 65536)      // ~122.9 KB

__device__ __forceinline__ uint32_t packbf(float a, float b) {
    __nv_bfloat162 v = __floats2bfloat162_rn(a, b);
    return *(uint32_t*)&v;
}
__device__ __forceinline__ void mma16816(float* d, const uint32_t* a,
                                         uint32_t b0, uint32_t b1) {
    asm("mma.sync.aligned.m16n8k16.row.col.f32.bf16.bf16.f32 "
        "{%0,%1,%2,%3}, {%4,%5,%6,%7}, {%8,%9}, {%0,%1,%2,%3};"
        : "+f"(d[0]), "+f"(d[1]), "+f"(d[2]), "+f"(d[3])
        : "r"(a[0]), "r"(a[1]), "r"(a[2]), "r"(a[3]), "r"(b0), "r"(b1));
}
__device__ __forceinline__ float ftanh(float x) {
    float y; asm("tanh.approx.f32 %0, %1;" : "=f"(y) : "f"(x)); return y;
}
__device__ __forceinline__ float fsigmoid(float x) {
    return fmaf(ftanh(0.5f * x), 0.5f, 0.5f);
}

__global__ __launch_bounds__(TPB, 1)
void lstm_kernel(const float* __restrict__ input,
                 const float* __restrict__ W_ih1, const float* __restrict__ W_hh1,
                 const float* __restrict__ b_ih1, const float* __restrict__ b_hh1,
                 const float* __restrict__ W_ih2, const float* __restrict__ W_hh2,
                 const float* __restrict__ b_ih2, const float* __restrict__ b_hh2,
                 const float* __restrict__ W_lin, const float* __restrict__ b_lin,
                 float* __restrict__ out)
{
    extern __shared__ __align__(16) char smem[];
    uint32_t (*hs)[NB][HSW] = (uint32_t (*)[NB][HSW])(smem + OFF_HS);
    float (*g1sh)[GSTR] = (float (*)[GSTR])(smem + OFF_G1);
    float (*g2sh)[GSTR] = (float (*)[GSTR])(smem + OFF_G2);
    float* wxs  = (float*)(smem + OFF_WX);
    float* b1s  = (float*)(smem + OFF_B1);
    float* b2s  = (float*)(smem + OFF_B2);
    float* wls  = (float*)(smem + OFF_WL);
    float* reds = (float*)(smem + OFF_RED);
    float* blns = (float*)(smem + OFF_BLN);
    uint4* a1lo = (uint4*)(smem + OFF_A1LO);
    uint4* a2lo = (uint4*)(smem + OFF_A2LO);

    const int tid  = threadIdx.x;
    const int w    = tid >> 5, lane = tid & 31;
    const int g    = lane >> 2, tq = lane & 3;
    const int R    = 16 * w + g;
    const int b0   = blockIdx.x * NB;
    const int ab   = tid >> 6;            // act batch (0..7)
    const int aj   = tid & 63;            // act hidden index

    // ---- Persistent hi A-fragments in regs; lo fragments -> SMEM ----
    uint32_t wa1[4][4];                    // W_hh1 hi
    uint32_t wa2[8][4];                    // [W_ih2|W_hh2] hi
    #pragma unroll
    for (int kt = 0; kt < 4; kt++) {
        uint32_t lo[4];
        #pragma unroll
        for (int r = 0; r < 4; r++) {
            int row = R + ((r & 1) ? 8 : 0);
            int cb  = kt * 16 + ((r >= 2) ? 8 : 0) + 2 * tq;
            float v0 = W_hh1[row * HID + cb], v1 = W_hh1[row * HID + cb + 1];
            float h0 = __bfloat162float(__float2bfloat16(v0));
            float h1 = __bfloat162float(__float2bfloat16(v1));
            wa1[kt][r] = packbf(h0, h1);
            lo[r]      = packbf(v0 - h0, v1 - h1);
        }
        a1lo[(w * 4 + kt) * 32 + lane] = make_uint4(lo[0], lo[1], lo[2], lo[3]);
    }
    #pragma unroll
    for (int kt = 0; kt < 8; kt++) {
        uint32_t lo[4];
        #pragma unroll
        for (int r = 0; r < 4; r++) {
            int row = R + ((r & 1) ? 8 : 0);
            int cb  = kt * 16 + ((r >= 2) ? 8 : 0) + 2 * tq;
            float v0 = (cb < 64) ? W_ih2[row * HID + cb]
                                 : W_hh2[row * HID + cb - 64];
            float v1 = (cb + 1 < 64) ? W_ih2[row * HID + cb + 1]
                                     : W_hh2[row * HID + cb + 1 - 64];
            float h0 = __bfloat162float(__float2bfloat16(v0));
            float h1 = __bfloat162float(__float2bfloat16(v1));
            wa2[kt][r] = packbf(h0, h1);
            lo[r]      = packbf(v0 - h0, v1 - h1);
        }
        a2lo[(w * 8 + kt) * 32 + lane] = make_uint4(lo[0], lo[1], lo[2], lo[3]);
    }

    // ---- Init SMEM state/scalars ----
    for (int i = tid; i < 2 * NB * HSW; i += TPB) ((uint32_t*)hs)[i] = 0;
    for (int i = tid; i < 256; i += TPB) {
        wxs[i] = W_ih1[i];
        b1s[i] = b_ih1[i] + b_hh1[i];
        b2s[i] = b_ih2[i] + b_hh2[i];
    }
    if (tid < HID) wls[tid] = W_lin[tid];
    if (tid == 0) blns[0] = b_lin[0];
    __syncthreads();

    float c1 = 0.f, c2 = 0.f;

    // ---- Peel act1(0): h1(-1)=0 so gates = wx*x(0) + bias ----
    {
        const float x0 = input[(b0 + ab) * SEQ + 0];
        float gI = fmaf(wxs[aj],       x0, b1s[aj]);
        float gF = fmaf(wxs[64 + aj],  x0, b1s[64 + aj]);
        float gG = fmaf(wxs[128 + aj], x0, b1s[128 + aj]);
        float gO = fmaf(wxs[192 + aj], x0, b1s[192 + aj]);
        float cn = fsigmoid(gF) * c1 + fsigmoid(gI) * ftanh(gG);
        c1 = cn;
        float h = fsigmoid(gO) * ftanh(cn);
        __nv_bfloat16 hi = __float2bfloat16(h);
        ((__nv_bfloat16*)&hs[0][ab][0])[aj] = hi;
        ((__nv_bfloat16*)&hs[1][ab][0])[aj] =
            __float2bfloat16(h - __bfloat162float(hi));
    }
    __syncthreads();

    const float blin = blns[0];

    for (int ts = 0; ts < SEQ; ts++) {
        const float xnext = (ts + 1 < SEQ)
            ? input[(b0 + ab) * SEQ + ts + 1] : 0.f;

        // ===== Phase A: out(t-1), MMA1(t+1), MMA2(t) =====
        if (ts > 0 && tid < NB)
            out[(b0 + tid) * SEQ + (ts - 1)] = reds[2 * tid] + reds[2 * tid + 1] + blin;

        // --- MMA1(t+1): gates1 = W_hh1 @ h1(t) (kt 0..3) ---
        {
            float d[4] = {0.f, 0.f, 0.f, 0.f};
            float e[4] = {0.f, 0.f, 0.f, 0.f};
            #pragma unroll
            for (int kt = 0; kt < 4; kt++) {
                uint32_t bh0 = hs[0][g][kt * 8 + tq];
                uint32_t bh1 = hs[0][g][kt * 8 + 4 + tq];
                uint32_t bl0 = hs[1][g][kt * 8 + tq];
                uint32_t bl1 = hs[1][g][kt * 8 + 4 + tq];
                uint4 alo = a1lo[(w * 4 + kt) * 32 + lane];
                mma16816(d, wa1[kt], bh0, bh1);
                mma16816(e, (uint32_t*)&alo, bh0, bh1);
                mma16816(e, wa1[kt], bl0, bl1);
            }
            g1sh[2 * tq    ][R    ] = d[0] + e[0];
            g1sh[2 * tq + 1][R    ] = d[1] + e[1];
            g1sh[2 * tq    ][R + 8] = d[2] + e[2];
            g1sh[2 * tq + 1][R + 8] = d[3] + e[3];
        }
        // --- MMA2(t): gates2 = [W_ih2|W_hh2] @ [h1(t); h2(t-1)] (kt 0..7) ---
        {
            float d[4] = {0.f, 0.f, 0.f, 0.f};
            float e[4] = {0.f, 0.f, 0.f, 0.f};
            #pragma unroll
            for (int kt = 0; kt < 8; kt++) {
                uint32_t bh0 = hs[0][g][kt * 8 + tq];
                uint32_t bh1 = hs[0][g][kt * 8 + 4 + tq];
                uint32_t bl0 = hs[1][g][kt * 8 + tq];
                uint32_t bl1 = hs[1][g][kt * 8 + 4 + tq];
                uint4 alo = a2lo[(w * 8 + kt) * 32 + lane];
                mma16816(d, wa2[kt], bh0, bh1);
                mma16816(e, (uint32_t*)&alo, bh0, bh1);
                mma16816(e, wa2[kt], bl0, bl1);
            }
            g2sh[2 * tq    ][R    ] = d[0] + e[0];
            g2sh[2 * tq + 1][R    ] = d[1] + e[1];
            g2sh[2 * tq    ][R + 8] = d[2] + e[2];
            g2sh[2 * tq + 1][R + 8] = d[3] + e[3];
        }
        __syncthreads();

        // ===== Phase B: act2(t) + act1(t+1) =====
        {   // act2(t)
            float gI = g2sh[ab][aj]       + b2s[aj];
            float gF = g2sh[ab][64 + aj]  + b2s[64 + aj];
            float gG = g2sh[ab][128 + aj] + b2s[128 + aj];
            float gO = g2sh[ab][192 + aj] + b2s[192 + aj];
            float cn = fsigmoid(gF) * c2 + fsigmoid(gI) * ftanh(gG);
            c2 = cn;
            float h = fsigmoid(gO) * ftanh(cn);
            __nv_bfloat16 hi = __float2bfloat16(h);
            ((__nv_bfloat16*)&hs[0][ab][0])[64 + aj] = hi;
            ((__nv_bfloat16*)&hs[1][ab][0])[64 + aj] =
                __float2bfloat16(h - __bfloat162float(hi));
            float vout = wls[aj] * h;
            #pragma unroll
            for (int off = 16; off; off >>= 1)
                vout += __shfl_down_sync(0xFFFFFFFFu, vout, off);
            if (lane == 0) reds[w] = vout;
        }
        if (ts + 1 < SEQ) {   // act1(t+1)
            float gI = g1sh[ab][aj]       + fmaf(wxs[aj],       xnext, b1s[aj]);
            float gF = g1sh[ab][64 + aj]  + fmaf(wxs[64 + aj],  xnext, b1s[64 + aj]);
            float gG = g1sh[ab][128 + aj] + fmaf(wxs[128 + aj], xnext, b1s[128 + aj]);
            float gO = g1sh[ab][192 + aj] + fmaf(wxs[192 + aj], xnext, b1s[192 + aj]);
            float cn = fsigmoid(gF) * c1 + fsigmoid(gI) * ftanh(gG);
            c1 = cn;
            float h = fsigmoid(gO) * ftanh(cn);
            __nv_bfloat16 hi = __float2bfloat16(h);
            ((__nv_bfloat16*)&hs[0][ab][0])[aj] = hi;
            ((__nv_bfloat16*)&hs[1][ab][0])[aj] =
                __float2bfloat16(h - __bfloat162float(hi));
        }
        __syncthreads();
    }

    // Final output (t = SEQ-1)
    if (tid < NB)
        out[(b0 + tid) * SEQ + (SEQ - 1)] = reds[2 * tid] + reds[2 * tid + 1] + blin;
}

extern "C" void kernel_launch(void* const* d_in, const int* in_sizes, int n_in,
                              void* d_out, int out_size) {
    (void)in_sizes; (void)n_in; (void)out_size;
    const float* input = (const float*)d_in[0];
    const float* W_ih1 = (const float*)d_in[1];
    const float* W_hh1 = (const float*)d_in[2];
    const float* b_ih1 = (const float*)d_in[3];
    const float* b_hh1 = (const float*)d_in[4];
    const float* W_ih2 = (const float*)d_in[5];
    const float* W_hh2 = (const float*)d_in[6];
    const float* b_ih2 = (const float*)d_in[7];
    const float* b_hh2 = (const float*)d_in[8];
    const float* W_lin = (const float*)d_in[9];
    const float* b_lin = (const float*)d_in[10];
    float* out = (float*)d_out;

    static bool attr_set = false;
    if (!attr_set) {
        cudaFuncSetAttribute(lstm_kernel,
                             cudaFuncAttributeMaxDynamicSharedMemorySize,
                             SMEM_TOTAL);
        attr_set = true;
    }
    lstm_kernel<<<NCTA, TPB, SMEM_TOTAL>>>(input, W_ih1, W_hh1, b_ih1, b_hh1,
                                           W_ih2, W_hh2, b_ih2, b_hh2,
                                           W_lin, b_lin, out);
}

// round 10
// speedup vs baseline: 1.5267x; 1.3165x over previous
#include <cuda_runtime.h>
#include <cuda_fp16.h>
#include <cstdint>

// 2-layer LSTM scan, B=1024, H=64, S=512, warp-level HMMA **fp16** 2-pass.
// R10: A = fp16 hi+lo entirely in registers (96 regs, no SMEM A traffic);
// h-state stored as SINGLE fp16 (B error ~2^-11, propagated ~1e-5 — on par
// with tanh.approx error). MMA per warp/step: 24 (was 36). SMEM traffic cut
// ~2.3x (was the binding pipe at L1=66%).
// Structure: 2 phases/step. Phase A: MMA1(t+1), MMA2(t). Phase B: act2(t) +
// act1(t+1). 128 CTAs x 512 threads; warp w owns gate rows [16w,16w+16).

#define HID 64
#define NB  8
#define TPB 512
#define BATCH 1024
#define SEQ 512
#define NCTA (BATCH/NB)      // 128
#define HSW 68               // hs row stride in words (64 h-pairs + pad)
#define GSTR 264             // gate buffer row stride (floats)

__device__ __forceinline__ uint32_t packh(float a, float b) {
    __half2 v = __floats2half2_rn(a, b);
    return *(uint32_t*)&v;
}
__device__ __forceinline__ void mma16816(float* d, const uint32_t* a,
                                         uint32_t b0, uint32_t b1) {
    asm("mma.sync.aligned.m16n8k16.row.col.f32.f16.f16.f32 "
        "{%0,%1,%2,%3}, {%4,%5,%6,%7}, {%8,%9}, {%0,%1,%2,%3};"
        : "+f"(d[0]), "+f"(d[1]), "+f"(d[2]), "+f"(d[3])
        : "r"(a[0]), "r"(a[1]), "r"(a[2]), "r"(a[3]), "r"(b0), "r"(b1));
}
__device__ __forceinline__ float ftanh(float x) {
    float y; asm("tanh.approx.f32 %0, %1;" : "=f"(y) : "f"(x)); return y;
}
__device__ __forceinline__ float fsigmoid(float x) {
    return fmaf(ftanh(0.5f * x), 0.5f, 0.5f);
}

__global__ __launch_bounds__(TPB, 1)
void lstm_kernel(const float* __restrict__ input,
                 const float* __restrict__ W_ih1, const float* __restrict__ W_hh1,
                 const float* __restrict__ b_ih1, const float* __restrict__ b_hh1,
                 const float* __restrict__ W_ih2, const float* __restrict__ W_hh2,
                 const float* __restrict__ b_ih2, const float* __restrict__ b_hh2,
                 const float* __restrict__ W_lin, const float* __restrict__ b_lin,
                 float* __restrict__ out)
{
    __shared__ uint32_t hs[NB][HSW];     // fp16 pairs; halfs 0..63=h1, 64..127=h2
    __shared__ float g1sh[NB][GSTR];     // layer-1 gates for step t+1
    __shared__ float g2sh[NB][GSTR];     // layer-2 gates for step t
    __shared__ float wxs[256], b1s[256], b2s[256], wls[HID];
    __shared__ float reds[16];
    __shared__ float blin;

    const int tid  = threadIdx.x;
    const int w    = tid >> 5, lane = tid & 31;
    const int g    = lane >> 2, tq = lane & 3;
    const int R    = 16 * w + g;
    const int b0   = blockIdx.x * NB;
    const int ab   = tid >> 6;            // act batch (0..7)
    const int aj   = tid & 63;            // act hidden index

    // ---- Persistent A-fragments, fp16 hi+lo, all in registers (96 regs) ----
    uint32_t wa1[2][4][4];                // [prec][kt][reg], W_hh1
    uint32_t wa2[2][8][4];                // [prec][kt][reg], [W_ih2|W_hh2]
    #pragma unroll
    for (int kt = 0; kt < 4; kt++) {
        #pragma unroll
        for (int r = 0; r < 4; r++) {
            int row = R + ((r & 1) ? 8 : 0);
            int cb  = kt * 16 + ((r >= 2) ? 8 : 0) + 2 * tq;
            float v0 = W_hh1[row * HID + cb], v1 = W_hh1[row * HID + cb + 1];
            float h0 = __half2float(__float2half_rn(v0));
            float h1 = __half2float(__float2half_rn(v1));
            wa1[0][kt][r] = packh(h0, h1);
            wa1[1][kt][r] = packh(v0 - h0, v1 - h1);
        }
    }
    #pragma unroll
    for (int kt = 0; kt < 8; kt++) {
        #pragma unroll
        for (int r = 0; r < 4; r++) {
            int row = R + ((r & 1) ? 8 : 0);
            int cb  = kt * 16 + ((r >= 2) ? 8 : 0) + 2 * tq;
            float v0 = (cb < 64) ? W_ih2[row * HID + cb]
                                 : W_hh2[row * HID + cb - 64];
            float v1 = (cb + 1 < 64) ? W_ih2[row * HID + cb + 1]
                                     : W_hh2[row * HID + cb + 1 - 64];
            float h0 = __half2float(__float2half_rn(v0));
            float h1 = __half2float(__float2half_rn(v1));
            wa2[0][kt][r] = packh(h0, h1);
            wa2[1][kt][r] = packh(v0 - h0, v1 - h1);
        }
    }

    // ---- Init SMEM ----
    for (int i = tid; i < NB * HSW; i += TPB) ((uint32_t*)hs)[i] = 0;
    for (int i = tid; i < 256; i += TPB) {
        wxs[i] = W_ih1[i];
        b1s[i] = b_ih1[i] + b_hh1[i];
        b2s[i] = b_ih2[i] + b_hh2[i];
    }
    if (tid < HID) wls[tid] = W_lin[tid];
    if (tid == 0) blin = b_lin[0];
    __syncthreads();

    float c1 = 0.f, c2 = 0.f;

    // ---- Peel act1(0): h1(-1)=0 so gates = wx*x(0) + bias ----
    {
        const float x0 = input[(b0 + ab) * SEQ + 0];
        float gI = fmaf(wxs[aj],       x0, b1s[aj]);
        float gF = fmaf(wxs[64 + aj],  x0, b1s[64 + aj]);
        float gG = fmaf(wxs[128 + aj], x0, b1s[128 + aj]);
        float gO = fmaf(wxs[192 + aj], x0, b1s[192 + aj]);
        float cn = fsigmoid(gF) * c1 + fsigmoid(gI) * ftanh(gG);
        c1 = cn;
        float h = fsigmoid(gO) * ftanh(cn);
        ((__half*)&hs[ab][0])[aj] = __float2half_rn(h);
    }
    __syncthreads();

    for (int ts = 0; ts < SEQ; ts++) {
        const float xnext = (ts + 1 < SEQ)
            ? input[(b0 + ab) * SEQ + ts + 1] : 0.f;

        // ===== Phase A: out(t-1), MMA1(t+1), MMA2(t) =====
        if (ts > 0 && tid < NB)
            out[(b0 + tid) * SEQ + (ts - 1)] = reds[2 * tid] + reds[2 * tid + 1] + blin;

        // --- MMA1(t+1): gates1 = W_hh1 @ h1(t) (kt 0..3, 2 passes) ---
        {
            float d[4] = {0.f, 0.f, 0.f, 0.f};
            float e[4] = {0.f, 0.f, 0.f, 0.f};
            #pragma unroll
            for (int kt = 0; kt < 4; kt++) {
                uint32_t bh0 = hs[g][kt * 8 + tq];
                uint32_t bh1 = hs[g][kt * 8 + 4 + tq];
                mma16816(d, wa1[0][kt], bh0, bh1);
                mma16816(e, wa1[1][kt], bh0, bh1);
            }
            g1sh[2 * tq    ][R    ] = d[0] + e[0];
            g1sh[2 * tq + 1][R    ] = d[1] + e[1];
            g1sh[2 * tq    ][R + 8] = d[2] + e[2];
            g1sh[2 * tq + 1][R + 8] = d[3] + e[3];
        }
        // --- MMA2(t): gates2 = [W_ih2|W_hh2] @ [h1(t); h2(t-1)] (kt 0..7) ---
        {
            float d[4] = {0.f, 0.f, 0.f, 0.f};
            float e[4] = {0.f, 0.f, 0.f, 0.f};
            #pragma unroll
            for (int kt = 0; kt < 8; kt++) {
                uint32_t bh0 = hs[g][kt * 8 + tq];
                uint32_t bh1 = hs[g][kt * 8 + 4 + tq];
                mma16816(d, wa2[0][kt], bh0, bh1);
                mma16816(e, wa2[1][kt], bh0, bh1);
            }
            g2sh[2 * tq    ][R    ] = d[0] + e[0];
            g2sh[2 * tq + 1][R    ] = d[1] + e[1];
            g2sh[2 * tq    ][R + 8] = d[2] + e[2];
            g2sh[2 * tq + 1][R + 8] = d[3] + e[3];
        }
        __syncthreads();

        // ===== Phase B: act2(t) + act1(t+1) =====
        {   // act2(t)
            float gI = g2sh[ab][aj]       + b2s[aj];
            float gF = g2sh[ab][64 + aj]  + b2s[64 + aj];
            float gG = g2sh[ab][128 + aj] + b2s[128 + aj];
            float gO = g2sh[ab][192 + aj] + b2s[192 + aj];
            float cn = fsigmoid(gF) * c2 + fsigmoid(gI) * ftanh(gG);
            c2 = cn;
            float h = fsigmoid(gO) * ftanh(cn);
            ((__half*)&hs[ab][0])[64 + aj] = __float2half_rn(h);
            float vout = wls[aj] * h;
            #pragma unroll
            for (int off = 16; off; off >>= 1)
                vout += __shfl_down_sync(0xFFFFFFFFu, vout, off);
            if (lane == 0) reds[w] = vout;
        }
        if (ts + 1 < SEQ) {   // act1(t+1)
            float gI = g1sh[ab][aj]       + fmaf(wxs[aj],       xnext, b1s[aj]);
            float gF = g1sh[ab][64 + aj]  + fmaf(wxs[64 + aj],  xnext, b1s[64 + aj]);
            float gG = g1sh[ab][128 + aj] + fmaf(wxs[128 + aj], xnext, b1s[128 + aj]);
            float gO = g1sh[ab][192 + aj] + fmaf(wxs[192 + aj], xnext, b1s[192 + aj]);
            float cn = fsigmoid(gF) * c1 + fsigmoid(gI) * ftanh(gG);
            c1 = cn;
            float h = fsigmoid(gO) * ftanh(cn);
            ((__half*)&hs[ab][0])[aj] = __float2half_rn(h);
        }
        __syncthreads();
    }

    // Final output (t = SEQ-1)
    if (tid < NB)
        out[(b0 + tid) * SEQ + (SEQ - 1)] = reds[2 * tid] + reds[2 * tid + 1] + blin;
}

extern "C" void kernel_launch(void* const* d_in, const int* in_sizes, int n_in,
                              void* d_out, int out_size) {
    (void)in_sizes; (void)n_in; (void)out_size;
    const float* input = (const float*)d_in[0];
    const float* W_ih1 = (const float*)d_in[1];
    const float* W_hh1 = (const float*)d_in[2];
    const float* b_ih1 = (const float*)d_in[3];
    const float* b_hh1 = (const float*)d_in[4];
    const float* W_ih2 = (const float*)d_in[5];
    const float* W_hh2 = (const float*)d_in[6];
    const float* b_ih2 = (const float*)d_in[7];
    const float* b_hh2 = (const float*)d_in[8];
    const float* W_lin = (const float*)d_in[9];
    const float* b_lin = (const float*)d_in[10];
    float* out = (float*)d_out;

    lstm_kernel<<<NCTA, TPB>>>(input, W_ih1, W_hh1, b_ih1, b_hh1,
                               W_ih2, W_hh2, b_ih2, b_hh2,
                               W_lin, b_lin, out);
}

// round 11
// speedup vs baseline: 2.6943x; 1.7648x over previous
#include <cuda_runtime.h>
#include <cuda_fp16.h>
#include <cstdint>

// 2-layer LSTM scan, B=1024, H=64, S=512. R11: in-warp activations.
// Warp w owns gate rows {gate*64 + 4w + jj}: after MMA, lane pair (L, L^16)
// holds all 4 gates for (j = 4w+jj, batches 2tq/2tq+1). Gates never hit SMEM;
// 1 __syncthreads()/step; h-state fp16 single-plane, parity double-buffered.
// A = single-pass fp16 in registers (48 regs). 12 HMMA/warp/step.
// 128 CTAs x 512 threads (16 warps); NB=8 batch columns per CTA.

#define HID 64
#define NB  8
#define TPB 512
#define BATCH 1024
#define SEQ 512
#define NCTA (BATCH/NB)      // 128
#define HSW 36               // h row stride in words (32 + 4 pad)
#define XSTR 513             // xs row stride in floats

__device__ __forceinline__ uint32_t packh(float a, float b) {
    __half2 v = __floats2half2_rn(a, b);
    return *(uint32_t*)&v;
}
__device__ __forceinline__ void mma16816(float* d, const uint32_t* a,
                                         uint32_t b0, uint32_t b1) {
    asm("mma.sync.aligned.m16n8k16.row.col.f32.f16.f16.f32 "
        "{%0,%1,%2,%3}, {%4,%5,%6,%7}, {%8,%9}, {%0,%1,%2,%3};"
        : "+f"(d[0]), "+f"(d[1]), "+f"(d[2]), "+f"(d[3])
        : "r"(a[0]), "r"(a[1]), "r"(a[2]), "r"(a[3]), "r"(b0), "r"(b1));
}
__device__ __forceinline__ float ftanh(float x) {
    float y; asm("tanh.approx.f32 %0, %1;" : "=f"(y) : "f"(x)); return y;
}

__global__ __launch_bounds__(TPB, 1)
void lstm_kernel(const float* __restrict__ input,
                 const float* __restrict__ W_ih1, const float* __restrict__ W_hh1,
                 const float* __restrict__ b_ih1, const float* __restrict__ b_hh1,
                 const float* __restrict__ W_ih2, const float* __restrict__ W_hh2,
                 const float* __restrict__ b_ih2, const float* __restrict__ b_hh2,
                 const float* __restrict__ W_lin, const float* __restrict__ b_lin,
                 float* __restrict__ out)
{
    __shared__ uint32_t hs1[2][NB][HSW];   // h1, fp16 pairs, parity-buffered
    __shared__ uint32_t hs2[2][NB][HSW];   // h2
    __shared__ float xs[NB * XSTR];        // staged inputs (padded rows)
    __shared__ float reds[2][128];         // out partials [parity][w*8 + b]

    const int tid  = threadIdx.x;
    const int w    = tid >> 5, lane = tid & 31;
    const int g    = lane >> 2, tq = lane & 3;
    const bool low = (g < 4);
    const int jj   = g & 3;
    const int j    = 4 * w + jj;           // hidden index this lane-pair owns
    const int b0   = blockIdx.x * NB;
    const int bmy  = 2 * tq + (low ? 0 : 1);   // batch this lane acts on

    // Gate rows: low pair = (i, G); high pair = (f, o)
    const int rowA = (low ? 0 : 1) * HID + j;   // i or f
    const int rowB = (low ? 2 : 3) * HID + j;   // G or o

    // ---- Persistent A-fragments, single fp16, registers only ----
    uint32_t wa1[4][4];                    // W_hh1 rows {rowA,rowB}(+k-halves)
    uint32_t wa2[8][4];                    // [W_ih2|W_hh2]
    #pragma unroll
    for (int kt = 0; kt < 4; kt++) {
        int cb = kt * 16 + 2 * tq;
        wa1[kt][0] = packh(W_hh1[rowA*HID+cb],   W_hh1[rowA*HID+cb+1]);
        wa1[kt][1] = packh(W_hh1[rowB*HID+cb],   W_hh1[rowB*HID+cb+1]);
        wa1[kt][2] = packh(W_hh1[rowA*HID+cb+8], W_hh1[rowA*HID+cb+9]);
        wa1[kt][3] = packh(W_hh1[rowB*HID+cb+8], W_hh1[rowB*HID+cb+9]);
    }
    #pragma unroll
    for (int kt = 0; kt < 8; kt++) {
        int cb = kt * 16 + 2 * tq;
        #pragma unroll
        for (int r = 0; r < 4; r++) {
            int row = (r & 1) ? rowB : rowA;
            int k   = cb + ((r >= 2) ? 8 : 0);
            float v0 = (k < HID)     ? W_ih2[row*HID + k]     : W_hh2[row*HID + k - HID];
            float v1 = (k + 1 < HID) ? W_ih2[row*HID + k + 1] : W_hh2[row*HID + k + 1 - HID];
            wa2[kt][r] = packh(v0, v1);
        }
    }

    // ---- Per-lane scalar constants ----
    const float bA1 = b_ih1[rowA] + b_hh1[rowA];
    const float bB1 = b_ih1[rowB] + b_hh1[rowB];
    const float bA2 = b_ih2[rowA] + b_hh2[rowA];
    const float bB2 = b_ih2[rowB] + b_hh2[rowB];
    const float wxA = W_ih1[rowA];
    const float wxB = W_ih1[rowB];
    const float wlj = W_lin[j];
    const float blin = b_lin[0];
    const float sB  = low ? 1.0f : 0.5f;   // G: full tanh; o: sigmoid
    const float pBm = low ? 1.0f : 0.5f;
    const float pBa = low ? 0.0f : 0.5f;

    // ---- Init SMEM ----
    for (int i = tid; i < 2 * NB * HSW; i += TPB) {
        ((uint32_t*)hs1)[i] = 0;
        ((uint32_t*)hs2)[i] = 0;
    }
    for (int i = tid; i < NB * SEQ; i += TPB) {
        int b = i >> 9, t = i & 511;
        xs[b * XSTR + t] = input[(b0 + b) * SEQ + i - b * SEQ + 0];
    }
    __syncthreads();

    float c1 = 0.f, c2 = 0.f;

    // ---- Peel act1(0): gates = wx*x(0) + bias (h1(-1)=0), write hs1[0] ----
    {
        float x0 = xs[(2*tq)     * XSTR + 0];
        float x1 = xs[(2*tq + 1) * XSTR + 0];
        float vA0 = fmaf(wxA, x0, bA1), vA1 = fmaf(wxA, x1, bA1);
        float vB0 = fmaf(wxB, x0, bB1), vB1 = fmaf(wxB, x1, bB1);
        float tA0 = ftanh(0.5f*vA0), tA1 = ftanh(0.5f*vA1);
        float tB0 = ftanh(sB*vB0),   tB1 = ftanh(sB*vB1);
        float uA0 = fmaf(0.5f,tA0,0.5f), uA1 = fmaf(0.5f,tA1,0.5f);
        float uB0 = fmaf(pBm,tB0,pBa),   uB1 = fmaf(pBm,tB1,pBa);
        float prod0 = uA0*uB0, prod1 = uA1*uB1;
        float r1 = __shfl_xor_sync(0xFFFFFFFFu, low ? prod1 : uA0, 16);
        float r2 = __shfl_xor_sync(0xFFFFFFFFu, low ? 0.f   : uB0, 16);
        float my_sf = low ? r1 : uA1;
        float my_pr = low ? prod0 : r1;
        float cn = fmaf(my_sf, c1, my_pr); c1 = cn;
        float tcn = ftanh(cn);
        float my_so = low ? r2 : uB1;
        float h = my_so * tcn;
        ((__half*)&hs1[0][bmy][0])[j] = __float2half_rn(h);
    }
    __syncthreads();

    for (int ts = 0; ts < SEQ; ts++) {
        const int p = ts & 1, pn = p ^ 1;

        // ---- finalize out(ts-1) ----
        if (ts > 0 && tid < NB) {
            float s = 0.f;
            #pragma unroll
            for (int ww = 0; ww < 16; ww++) s += reds[pn][ww * 8 + tid];
            out[(b0 + tid) * SEQ + (ts - 1)] = s + blin;
        }

        // ---- MMA2(t): [W_ih2|W_hh2] @ [h1(t); h2(t-1)] ----
        float d[4]  = {0.f,0.f,0.f,0.f};
        float d2[4] = {0.f,0.f,0.f,0.f};
        uint32_t cb0[4], cb1[4];               // cached h1 frags for MMA1
        #pragma unroll
        for (int kt = 0; kt < 4; kt++) {
            uint32_t bh0 = hs1[p][g][kt * 8 + tq];
            uint32_t bh1 = hs1[p][g][kt * 8 + 4 + tq];
            cb0[kt] = bh0; cb1[kt] = bh1;
            mma16816((kt & 1) ? d2 : d, wa2[kt], bh0, bh1);
        }
        #pragma unroll
        for (int kt = 4; kt < 8; kt++) {
            uint32_t bh0 = hs2[pn][g][(kt - 4) * 8 + tq];
            uint32_t bh1 = hs2[pn][g][(kt - 4) * 8 + 4 + tq];
            mma16816((kt & 1) ? d2 : d, wa2[kt], bh0, bh1);
        }
        #pragma unroll
        for (int i = 0; i < 4; i++) d[i] += d2[i];

        // ---- act2(t): in-warp; writes hs2[p], reds[p] ----
        {
            float vA0 = d[0] + bA2, vA1 = d[1] + bA2;
            float vB0 = d[2] + bB2, vB1 = d[3] + bB2;
            float tA0 = ftanh(0.5f*vA0), tA1 = ftanh(0.5f*vA1);
            float tB0 = ftanh(sB*vB0),   tB1 = ftanh(sB*vB1);
            float uA0 = fmaf(0.5f,tA0,0.5f), uA1 = fmaf(0.5f,tA1,0.5f);
            float uB0 = fmaf(pBm,tB0,pBa),   uB1 = fmaf(pBm,tB1,pBa);
            float prod0 = uA0*uB0, prod1 = uA1*uB1;
            float r1 = __shfl_xor_sync(0xFFFFFFFFu, low ? prod1 : uA0, 16);
            float r2 = __shfl_xor_sync(0xFFFFFFFFu, low ? 0.f   : uB0, 16);
            float my_sf = low ? r1 : uA1;
            float my_pr = low ? prod0 : r1;
            float cn = fmaf(my_sf, c2, my_pr); c2 = cn;
            float tcn = ftanh(cn);
            float my_so = low ? r2 : uB1;
            float h = my_so * tcn;
            ((__half*)&hs2[p][bmy][0])[j] = __float2half_rn(h);
            // out partial: reduce wlj*h over jj (lanes 4g+tq, g-quad)
            float v = wlj * h;
            v += __shfl_xor_sync(0xFFFFFFFFu, v, 4);
            v += __shfl_xor_sync(0xFFFFFFFFu, v, 8);
            if ((lane & 12) == 0) reds[p][w * 8 + bmy] = v;
        }

        // ---- MMA1(t+1) + act1(t+1) ----
        if (ts + 1 < SEQ) {
            float e[4]  = {0.f,0.f,0.f,0.f};
            float e2[4] = {0.f,0.f,0.f,0.f};
            #pragma unroll
            for (int kt = 0; kt < 4; kt++)
                mma16816((kt & 1) ? e2 : e, wa1[kt], cb0[kt], cb1[kt]);
            #pragma unroll
            for (int i = 0; i < 4; i++) e[i] += e2[i];

            float x0 = xs[(2*tq)     * XSTR + ts + 1];
            float x1 = xs[(2*tq + 1) * XSTR + ts + 1];
            float vA0 = fmaf(wxA, x0, e[0] + bA1), vA1 = fmaf(wxA, x1, e[1] + bA1);
            float vB0 = fmaf(wxB, x0, e[2] + bB1), vB1 = fmaf(wxB, x1, e[3] + bB1);
            float tA0 = ftanh(0.5f*vA0), tA1 = ftanh(0.5f*vA1);
            float tB0 = ftanh(sB*vB0),   tB1 = ftanh(sB*vB1);
            float uA0 = fmaf(0.5f,tA0,0.5f), uA1 = fmaf(0.5f,tA1,0.5f);
            float uB0 = fmaf(pBm,tB0,pBa),   uB1 = fmaf(pBm,tB1,pBa);
            float prod0 = uA0*uB0, prod1 = uA1*uB1;
            float r1 = __shfl_xor_sync(0xFFFFFFFFu, low ? prod1 : uA0, 16);
            float r2 = __shfl_xor_sync(0xFFFFFFFFu, low ? 0.f   : uB0, 16);
            float my_sf = low ? r1 : uA1;
            float my_pr = low ? prod0 : r1;
            float cn = fmaf(my_sf, c1, my_pr); c1 = cn;
            float tcn = ftanh(cn);
            float my_so = low ? r2 : uB1;
            float h = my_so * tcn;
            ((__half*)&hs1[pn][bmy][0])[j] = __float2half_rn(h);
        }
        __syncthreads();
    }

    // ---- finalize out(SEQ-1) ----
    if (tid < NB) {
        float s = 0.f;
        #pragma unroll
        for (int ww = 0; ww < 16; ww++) s += reds[(SEQ - 1) & 1][ww * 8 + tid];
        out[(b0 + tid) * SEQ + (SEQ - 1)] = s + blin;
    }
}

extern "C" void kernel_launch(void* const* d_in, const int* in_sizes, int n_in,
                              void* d_out, int out_size) {
    (void)in_sizes; (void)n_in; (void)out_size;
    const float* input = (const float*)d_in[0];
    const float* W_ih1 = (const float*)d_in[1];
    const float* W_hh1 = (const float*)d_in[2];
    const float* b_ih1 = (const float*)d_in[3];
    const float* b_hh1 = (const float*)d_in[4];
    const float* W_ih2 = (const float*)d_in[5];
    const float* W_hh2 = (const float*)d_in[6];
    const float* b_ih2 = (const float*)d_in[7];
    const float* b_hh2 = (const float*)d_in[8];
    const float* W_lin = (const float*)d_in[9];
    const float* b_lin = (const float*)d_in[10];
    float* out = (float*)d_out;

    lstm_kernel<<<NCTA, TPB>>>(input, W_ih1, W_hh1, b_ih1, b_hh1,
                               W_ih2, W_hh2, b_ih2, b_hh2,
                               W_lin, b_lin, out);
}

// round 12
// speedup vs baseline: 2.8953x; 1.0746x over previous
#include <cuda_runtime.h>
#include <cuda_fp16.h>
#include <cstdint>

// 2-layer LSTM scan, B=1024, H=64, S=512. R12 = R11 + vectorized h exchange.
// - h words permuted per batch row: word wd -> pos q=(wd&3)*8+(wd>>2), so each
//   lane's MMA B-frags are 8 contiguous words: 2x LDS.128 per operand half.
// - x staged transposed [t][b]: one LDS.64 per act.
// - ts loop unrolled x2: parity addresses constant-fold.
// Warp w owns gate rows {gate*64 + 4w + jj}; lane pair (L, L^16) holds all 4
// gates for (j, 2 batches); in-warp activations; 1 __syncthreads()/step.
// A = single-pass fp16 in registers. 12 HMMA/warp/step.

#define HID 64
#define NB  8
#define TPB 512
#define BATCH 1024
#define SEQ 512
#define NCTA (BATCH/NB)      // 128
#define HSW 36               // h row stride in words (32 + 4 pad)

__device__ __forceinline__ uint32_t packh(float a, float b) {
    __half2 v = __floats2half2_rn(a, b);
    return *(uint32_t*)&v;
}
__device__ __forceinline__ void mma16816(float* d, const uint32_t* a,
                                         uint32_t b0, uint32_t b1) {
    asm("mma.sync.aligned.m16n8k16.row.col.f32.f16.f16.f32 "
        "{%0,%1,%2,%3}, {%4,%5,%6,%7}, {%8,%9}, {%0,%1,%2,%3};"
        : "+f"(d[0]), "+f"(d[1]), "+f"(d[2]), "+f"(d[3])
        : "r"(a[0]), "r"(a[1]), "r"(a[2]), "r"(a[3]), "r"(b0), "r"(b1));
}
__device__ __forceinline__ float ftanh(float x) {
    float y; asm("tanh.approx.f32 %0, %1;" : "=f"(y) : "f"(x)); return y;
}

__global__ __launch_bounds__(TPB, 1)
void lstm_kernel(const float* __restrict__ input,
                 const float* __restrict__ W_ih1, const float* __restrict__ W_hh1,
                 const float* __restrict__ b_ih1, const float* __restrict__ b_hh1,
                 const float* __restrict__ W_ih2, const float* __restrict__ W_hh2,
                 const float* __restrict__ b_ih2, const float* __restrict__ b_hh2,
                 const float* __restrict__ W_lin, const float* __restrict__ b_lin,
                 float* __restrict__ out)
{
    __shared__ uint32_t hs1[2][NB][HSW];   // h1, permuted fp16 pairs, parity-buffered
    __shared__ uint32_t hs2[2][NB][HSW];   // h2
    __shared__ float xs2[SEQ * NB];        // inputs transposed [t][b] (16 KB)
    __shared__ float reds[2][128];         // out partials [parity][w*8 + b]

    const int tid  = threadIdx.x;
    const int w    = tid >> 5, lane = tid & 31;
    const int g    = lane >> 2, tq = lane & 3;
    const bool low = (g < 4);
    const int jj   = g & 3;
    const int j    = 4 * w + jj;           // hidden index this lane-pair owns
    const int b0   = blockIdx.x * NB;
    const int bmy  = 2 * tq + (low ? 0 : 1);   // batch this lane acts on

    // Permuted store offset for h[j] within a batch row (bytes)
    const int wd   = j >> 1;
    const int hq   = (wd & 3) * 8 + (wd >> 2);
    const int hoff = hq * 4 + (j & 1) * 2;

    // Gate rows: low pair = (i, G); high pair = (f, o)
    const int rowA = (low ? 0 : 1) * HID + j;   // i or f
    const int rowB = (low ? 2 : 3) * HID + j;   // G or o

    // ---- Persistent A-fragments, single fp16, registers only ----
    uint32_t wa1[4][4];                    // W_hh1
    uint32_t wa2[8][4];                    // [W_ih2|W_hh2]
    #pragma unroll
    for (int kt = 0; kt < 4; kt++) {
        int cb = kt * 16 + 2 * tq;
        wa1[kt][0] = packh(W_hh1[rowA*HID+cb],   W_hh1[rowA*HID+cb+1]);
        wa1[kt][1] = packh(W_hh1[rowB*HID+cb],   W_hh1[rowB*HID+cb+1]);
        wa1[kt][2] = packh(W_hh1[rowA*HID+cb+8], W_hh1[rowA*HID+cb+9]);
        wa1[kt][3] = packh(W_hh1[rowB*HID+cb+8], W_hh1[rowB*HID+cb+9]);
    }
    #pragma unroll
    for (int kt = 0; kt < 8; kt++) {
        int cb = kt * 16 + 2 * tq;
        #pragma unroll
        for (int r = 0; r < 4; r++) {
            int row = (r & 1) ? rowB : rowA;
            int k   = cb + ((r >= 2) ? 8 : 0);
            float v0 = (k < HID)     ? W_ih2[row*HID + k]     : W_hh2[row*HID + k - HID];
            float v1 = (k + 1 < HID) ? W_ih2[row*HID + k + 1] : W_hh2[row*HID + k + 1 - HID];
            wa2[kt][r] = packh(v0, v1);
        }
    }

    // ---- Per-lane scalar constants ----
    const float bA1 = b_ih1[rowA] + b_hh1[rowA];
    const float bB1 = b_ih1[rowB] + b_hh1[rowB];
    const float bA2 = b_ih2[rowA] + b_hh2[rowA];
    const float bB2 = b_ih2[rowB] + b_hh2[rowB];
    const float wxA = W_ih1[rowA];
    const float wxB = W_ih1[rowB];
    const float wlj = W_lin[j];
    const float blin = b_lin[0];
    const float sB  = low ? 1.0f : 0.5f;   // G: full tanh; o: sigmoid
    const float pBm = low ? 1.0f : 0.5f;
    const float pBa = low ? 0.0f : 0.5f;

    // ---- Init SMEM ----
    for (int i = tid; i < 2 * NB * HSW; i += TPB) {
        ((uint32_t*)hs1)[i] = 0;
        ((uint32_t*)hs2)[i] = 0;
    }
    for (int i = tid; i < NB * SEQ; i += TPB) {
        int b = i >> 9, t = i & 511;       // coalesced gmem read
        xs2[t * NB + b] = input[(b0 + b) * SEQ + t];
    }
    __syncthreads();

    float c1 = 0.f, c2 = 0.f;

    // ---- Peel act1(0): gates = wx*x(0) + bias (h1(-1)=0), write hs1[0] ----
    {
        float2 xp = *(const float2*)&xs2[0 * NB + 2 * tq];
        float vA0 = fmaf(wxA, xp.x, bA1), vA1 = fmaf(wxA, xp.y, bA1);
        float vB0 = fmaf(wxB, xp.x, bB1), vB1 = fmaf(wxB, xp.y, bB1);
        float tA0 = ftanh(0.5f*vA0), tA1 = ftanh(0.5f*vA1);
        float tB0 = ftanh(sB*vB0),   tB1 = ftanh(sB*vB1);
        float uA0 = fmaf(0.5f,tA0,0.5f), uA1 = fmaf(0.5f,tA1,0.5f);
        float uB0 = fmaf(pBm,tB0,pBa),   uB1 = fmaf(pBm,tB1,pBa);
        float prod0 = uA0*uB0, prod1 = uA1*uB1;
        float r1 = __shfl_xor_sync(0xFFFFFFFFu, low ? prod1 : uA0, 16);
        float r2 = __shfl_xor_sync(0xFFFFFFFFu, low ? 0.f   : uB0, 16);
        float my_sf = low ? r1 : uA1;
        float my_pr = low ? prod0 : r1;
        float cn = fmaf(my_sf, c1, my_pr); c1 = cn;
        float tcn = ftanh(cn);
        float my_so = low ? r2 : uB1;
        float h = my_so * tcn;
        *(__half*)((char*)&hs1[0][bmy][0] + hoff) = __float2half_rn(h);
    }
    __syncthreads();

    #pragma unroll 2
    for (int ts = 0; ts < SEQ; ts++) {
        const int p = ts & 1, pn = p ^ 1;

        // ---- finalize out(ts-1) ----
        if (ts > 0 && tid < NB) {
            float s = 0.f;
            #pragma unroll
            for (int ww = 0; ww < 16; ww++) s += reds[pn][ww * 8 + tid];
            out[(b0 + tid) * SEQ + (ts - 1)] = s + blin;
        }

        // ---- Load B-frags: 2x LDS.128 per operand half ----
        const uint4* h1p = (const uint4*)&hs1[p][g][tq * 8];
        const uint4* h2p = (const uint4*)&hs2[pn][g][tq * 8];
        uint4 h1a = h1p[0], h1b = h1p[1];
        uint4 h2a = h2p[0], h2b = h2p[1];

        // ---- MMA2(t): [W_ih2|W_hh2] @ [h1(t); h2(t-1)] ----
        float d[4]  = {0.f,0.f,0.f,0.f};
        float d2[4] = {0.f,0.f,0.f,0.f};
        mma16816(d,  wa2[0], h1a.x, h1a.y);
        mma16816(d2, wa2[1], h1a.z, h1a.w);
        mma16816(d,  wa2[2], h1b.x, h1b.y);
        mma16816(d2, wa2[3], h1b.z, h1b.w);
        mma16816(d,  wa2[4], h2a.x, h2a.y);
        mma16816(d2, wa2[5], h2a.z, h2a.w);
        mma16816(d,  wa2[6], h2b.x, h2b.y);
        mma16816(d2, wa2[7], h2b.z, h2b.w);
        #pragma unroll
        for (int i = 0; i < 4; i++) d[i] += d2[i];

        // ---- act2(t): in-warp; writes hs2[p], reds[p] ----
        {
            float vA0 = d[0] + bA2, vA1 = d[1] + bA2;
            float vB0 = d[2] + bB2, vB1 = d[3] + bB2;
            float tA0 = ftanh(0.5f*vA0), tA1 = ftanh(0.5f*vA1);
            float tB0 = ftanh(sB*vB0),   tB1 = ftanh(sB*vB1);
            float uA0 = fmaf(0.5f,tA0,0.5f), uA1 = fmaf(0.5f,tA1,0.5f);
            float uB0 = fmaf(pBm,tB0,pBa),   uB1 = fmaf(pBm,tB1,pBa);
            float prod0 = uA0*uB0, prod1 = uA1*uB1;
            float r1 = __shfl_xor_sync(0xFFFFFFFFu, low ? prod1 : uA0, 16);
            float r2 = __shfl_xor_sync(0xFFFFFFFFu, low ? 0.f   : uB0, 16);
            float my_sf = low ? r1 : uA1;
            float my_pr = low ? prod0 : r1;
            float cn = fmaf(my_sf, c2, my_pr); c2 = cn;
            float tcn = ftanh(cn);
            float my_so = low ? r2 : uB1;
            float h = my_so * tcn;
            *(__half*)((char*)&hs2[p][bmy][0] + hoff) = __float2half_rn(h);
            float v = wlj * h;
            v += __shfl_xor_sync(0xFFFFFFFFu, v, 4);
            v += __shfl_xor_sync(0xFFFFFFFFu, v, 8);
            if ((lane & 12) == 0) reds[p][w * 8 + bmy] = v;
        }

        // ---- MMA1(t+1) + act1(t+1): reuses h1a/h1b frags ----
        if (ts + 1 < SEQ) {
            float e[4]  = {0.f,0.f,0.f,0.f};
            float e2[4] = {0.f,0.f,0.f,0.f};
            mma16816(e,  wa1[0], h1a.x, h1a.y);
            mma16816(e2, wa1[1], h1a.z, h1a.w);
            mma16816(e,  wa1[2], h1b.x, h1b.y);
            mma16816(e2, wa1[3], h1b.z, h1b.w);
            #pragma unroll
            for (int i = 0; i < 4; i++) e[i] += e2[i];

            float2 xp = *(const float2*)&xs2[(ts + 1) * NB + 2 * tq];
            float vA0 = fmaf(wxA, xp.x, e[0] + bA1), vA1 = fmaf(wxA, xp.y, e[1] + bA1);
            float vB0 = fmaf(wxB, xp.x, e[2] + bB1), vB1 = fmaf(wxB, xp.y, e[3] + bB1);
            float tA0 = ftanh(0.5f*vA0), tA1 = ftanh(0.5f*vA1);
            float tB0 = ftanh(sB*vB0),   tB1 = ftanh(sB*vB1);
            float uA0 = fmaf(0.5f,tA0,0.5f), uA1 = fmaf(0.5f,tA1,0.5f);
            float uB0 = fmaf(pBm,tB0,pBa),   uB1 = fmaf(pBm,tB1,pBa);
            float prod0 = uA0*uB0, prod1 = uA1*uB1;
            float r1 = __shfl_xor_sync(0xFFFFFFFFu, low ? prod1 : uA0, 16);
            float r2 = __shfl_xor_sync(0xFFFFFFFFu, low ? 0.f   : uB0, 16);
            float my_sf = low ? r1 : uA1;
            float my_pr = low ? prod0 : r1;
            float cn = fmaf(my_sf, c1, my_pr); c1 = cn;
            float tcn = ftanh(cn);
            float my_so = low ? r2 : uB1;
            float h = my_so * tcn;
            *(__half*)((char*)&hs1[pn][bmy][0] + hoff) = __float2half_rn(h);
        }
        __syncthreads();
    }

    // ---- finalize out(SEQ-1) ----
    if (tid < NB) {
        float s = 0.f;
        #pragma unroll
        for (int ww = 0; ww < 16; ww++) s += reds[(SEQ - 1) & 1][ww * 8 + tid];
        out[(b0 + tid) * SEQ + (SEQ - 1)] = s + blin;
    }
}

extern "C" void kernel_launch(void* const* d_in, const int* in_sizes, int n_in,
                              void* d_out, int out_size) {
    (void)in_sizes; (void)n_in; (void)out_size;
    const float* input = (const float*)d_in[0];
    const float* W_ih1 = (const float*)d_in[1];
    const float* W_hh1 = (const float*)d_in[2];
    const float* b_ih1 = (const float*)d_in[3];
    const float* b_hh1 = (const float*)d_in[4];
    const float* W_ih2 = (const float*)d_in[5];
    const float* W_hh2 = (const float*)d_in[6];
    const float* b_ih2 = (const float*)d_in[7];
    const float* b_hh2 = (const float*)d_in[8];
    const float* W_lin = (const float*)d_in[9];
    const float* b_lin = (const float*)d_in[10];
    float* out = (float*)d_out;

    lstm_kernel<<<NCTA, TPB>>>(input, W_ih1, W_hh1, b_ih1, b_hh1,
                               W_ih2, W_hh2, b_ih2, b_hh2,
                               W_lin, b_lin, out);
}

// round 13
// speedup vs baseline: 2.9761x; 1.0279x over previous
#include <cuda_runtime.h>
#include <cuda_fp16.h>
#include <cstdint>

// 2-layer LSTM scan, B=1024, H=64, S=512. R13 = R12 + chain shortening:
//  - step order: LDS frags -> out -> MMA2 -> MMA1 -> act2 -> act1, so MMA1's
//    latency retires under act2's MUFU/shfl chain.
//  - biases (and wx*x term) folded into MMA accumulator init.
// Warp w owns gate rows {gate*64 + 4w + jj}; lane pair (L, L^16) holds all 4
// gates for (j, 2 batches); in-warp activations; 1 __syncthreads()/step.
// h permuted fp16 single-plane (2x LDS.128/operand), x transposed [t][b].
// A = single-pass fp16 in registers. 12 HMMA/warp/step.

#define HID 64
#define NB  8
#define TPB 512
#define BATCH 1024
#define SEQ 512
#define NCTA (BATCH/NB)      // 128
#define HSW 36               // h row stride in words (32 + 4 pad)

__device__ __forceinline__ uint32_t packh(float a, float b) {
    __half2 v = __floats2half2_rn(a, b);
    return *(uint32_t*)&v;
}
__device__ __forceinline__ void mma16816(float* d, const uint32_t* a,
                                         uint32_t b0, uint32_t b1) {
    asm("mma.sync.aligned.m16n8k16.row.col.f32.f16.f16.f32 "
        "{%0,%1,%2,%3}, {%4,%5,%6,%7}, {%8,%9}, {%0,%1,%2,%3};"
        : "+f"(d[0]), "+f"(d[1]), "+f"(d[2]), "+f"(d[3])
        : "r"(a[0]), "r"(a[1]), "r"(a[2]), "r"(a[3]), "r"(b0), "r"(b1));
}
__device__ __forceinline__ float ftanh(float x) {
    float y; asm("tanh.approx.f32 %0, %1;" : "=f"(y) : "f"(x)); return y;
}

__global__ __launch_bounds__(TPB, 1)
void lstm_kernel(const float* __restrict__ input,
                 const float* __restrict__ W_ih1, const float* __restrict__ W_hh1,
                 const float* __restrict__ b_ih1, const float* __restrict__ b_hh1,
                 const float* __restrict__ W_ih2, const float* __restrict__ W_hh2,
                 const float* __restrict__ b_ih2, const float* __restrict__ b_hh2,
                 const float* __restrict__ W_lin, const float* __restrict__ b_lin,
                 float* __restrict__ out)
{
    __shared__ uint32_t hs1[2][NB][HSW];   // h1, permuted fp16 pairs, parity-buffered
    __shared__ uint32_t hs2[2][NB][HSW];   // h2
    __shared__ float xs2[SEQ * NB];        // inputs transposed [t][b] (16 KB)
    __shared__ float reds[2][128];         // out partials [parity][w*8 + b]

    const int tid  = threadIdx.x;
    const int w    = tid >> 5, lane = tid & 31;
    const int g    = lane >> 2, tq = lane & 3;
    const bool low = (g < 4);
    const int jj   = g & 3;
    const int j    = 4 * w + jj;           // hidden index this lane-pair owns
    const int b0   = blockIdx.x * NB;
    const int bmy  = 2 * tq + (low ? 0 : 1);   // batch this lane acts on
    const bool red_lane = ((lane & 12) == 0);

    // Permuted store offset for h[j] within a batch row (bytes)
    const int wd   = j >> 1;
    const int hq   = (wd & 3) * 8 + (wd >> 2);
    const int hoff = hq * 4 + (j & 1) * 2;

    // Gate rows: low pair = (i, G); high pair = (f, o)
    const int rowA = (low ? 0 : 1) * HID + j;   // i or f
    const int rowB = (low ? 2 : 3) * HID + j;   // G or o

    // ---- Persistent A-fragments, single fp16, registers only ----
    uint32_t wa1[4][4];                    // W_hh1
    uint32_t wa2[8][4];                    // [W_ih2|W_hh2]
    #pragma unroll
    for (int kt = 0; kt < 4; kt++) {
        int cb = kt * 16 + 2 * tq;
        wa1[kt][0] = packh(W_hh1[rowA*HID+cb],   W_hh1[rowA*HID+cb+1]);
        wa1[kt][1] = packh(W_hh1[rowB*HID+cb],   W_hh1[rowB*HID+cb+1]);
        wa1[kt][2] = packh(W_hh1[rowA*HID+cb+8], W_hh1[rowA*HID+cb+9]);
        wa1[kt][3] = packh(W_hh1[rowB*HID+cb+8], W_hh1[rowB*HID+cb+9]);
    }
    #pragma unroll
    for (int kt = 0; kt < 8; kt++) {
        int cb = kt * 16 + 2 * tq;
        #pragma unroll
        for (int r = 0; r < 4; r++) {
            int row = (r & 1) ? rowB : rowA;
            int k   = cb + ((r >= 2) ? 8 : 0);
            float v0 = (k < HID)     ? W_ih2[row*HID + k]     : W_hh2[row*HID + k - HID];
            float v1 = (k + 1 < HID) ? W_ih2[row*HID + k + 1] : W_hh2[row*HID + k + 1 - HID];
            wa2[kt][r] = packh(v0, v1);
        }
    }

    // ---- Per-lane scalar constants ----
    const float bA1 = b_ih1[rowA] + b_hh1[rowA];
    const float bB1 = b_ih1[rowB] + b_hh1[rowB];
    const float bA2 = b_ih2[rowA] + b_hh2[rowA];
    const float bB2 = b_ih2[rowB] + b_hh2[rowB];
    const float wxA = W_ih1[rowA];
    const float wxB = W_ih1[rowB];
    const float wlj = W_lin[j];
    const float blin = b_lin[0];
    const float sB  = low ? 1.0f : 0.5f;   // G: full tanh; o: sigmoid
    const float pBm = low ? 1.0f : 0.5f;
    const float pBa = low ? 0.0f : 0.5f;

    // ---- Init SMEM ----
    for (int i = tid; i < 2 * NB * HSW; i += TPB) {
        ((uint32_t*)hs1)[i] = 0;
        ((uint32_t*)hs2)[i] = 0;
    }
    for (int i = tid; i < NB * SEQ; i += TPB) {
        int b = i >> 9, t = i & 511;       // coalesced gmem read
        xs2[t * NB + b] = input[(b0 + b) * SEQ + t];
    }
    __syncthreads();

    float c1 = 0.f, c2 = 0.f;

    // ---- Peel act1(0): gates = wx*x(0) + bias (h1(-1)=0), write hs1[0] ----
    {
        float2 xp = *(const float2*)&xs2[0 * NB + 2 * tq];
        float vA0 = fmaf(wxA, xp.x, bA1), vA1 = fmaf(wxA, xp.y, bA1);
        float vB0 = fmaf(wxB, xp.x, bB1), vB1 = fmaf(wxB, xp.y, bB1);
        float tA0 = ftanh(0.5f*vA0), tA1 = ftanh(0.5f*vA1);
        float tB0 = ftanh(sB*vB0),   tB1 = ftanh(sB*vB1);
        float uA0 = fmaf(0.5f,tA0,0.5f), uA1 = fmaf(0.5f,tA1,0.5f);
        float uB0 = fmaf(pBm,tB0,pBa),   uB1 = fmaf(pBm,tB1,pBa);
        float prod0 = uA0*uB0, prod1 = uA1*uB1;
        float r1 = __shfl_xor_sync(0xFFFFFFFFu, low ? prod1 : uA0, 16);
        float r2 = __shfl_xor_sync(0xFFFFFFFFu, low ? 0.f   : uB0, 16);
        float my_sf = low ? r1 : uA1;
        float my_pr = low ? prod0 : r1;
        float cn = fmaf(my_sf, c1, my_pr); c1 = cn;
        float tcn = ftanh(cn);
        float my_so = low ? r2 : uB1;
        float h = my_so * tcn;
        *(__half*)((char*)&hs1[0][bmy][0] + hoff) = __float2half_rn(h);
    }
    __syncthreads();

    #pragma unroll 2
    for (int ts = 0; ts < SEQ; ts++) {
        const int p = ts & 1, pn = p ^ 1;

        // ---- Load B-frags: 2x LDS.128 per operand half ----
        const uint4* h1p = (const uint4*)&hs1[p][g][tq * 8];
        const uint4* h2p = (const uint4*)&hs2[pn][g][tq * 8];
        uint4 h1a = h1p[0], h1b = h1p[1];
        uint4 h2a = h2p[0], h2b = h2p[1];

        // ---- finalize out(ts-1) (independent of this step's compute) ----
        if (ts > 0 && tid < NB) {
            float s = 0.f;
            #pragma unroll
            for (int ww = 0; ww < 16; ww++) s += reds[pn][ww * 8 + tid];
            out[(b0 + tid) * SEQ + (ts - 1)] = s + blin;
        }

        // ---- MMA2(t): bias-initialized accumulators ----
        float d[4]  = {bA2, bA2, bB2, bB2};
        float d2[4] = {0.f, 0.f, 0.f, 0.f};
        mma16816(d,  wa2[0], h1a.x, h1a.y);
        mma16816(d2, wa2[1], h1a.z, h1a.w);
        mma16816(d,  wa2[2], h1b.x, h1b.y);
        mma16816(d2, wa2[3], h1b.z, h1b.w);
        mma16816(d,  wa2[4], h2a.x, h2a.y);
        mma16816(d2, wa2[5], h2a.z, h2a.w);
        mma16816(d,  wa2[6], h2b.x, h2b.y);
        mma16816(d2, wa2[7], h2b.z, h2b.w);

        // ---- MMA1(t+1): issued BEFORE act2 so its latency hides under it.
        //      Accumulators init with bias + wx*x(t+1). ----
        float e[4], e2[4];
        const bool has_next = (ts + 1 < SEQ);
        if (has_next) {
            float2 xp = *(const float2*)&xs2[(ts + 1) * NB + 2 * tq];
            e[0] = fmaf(wxA, xp.x, bA1); e[1] = fmaf(wxA, xp.y, bA1);
            e[2] = fmaf(wxB, xp.x, bB1); e[3] = fmaf(wxB, xp.y, bB1);
            e2[0] = e2[1] = e2[2] = e2[3] = 0.f;
            mma16816(e,  wa1[0], h1a.x, h1a.y);
            mma16816(e2, wa1[1], h1a.z, h1a.w);
            mma16816(e,  wa1[2], h1b.x, h1b.y);
            mma16816(e2, wa1[3], h1b.z, h1b.w);
        }

        // ---- act2(t): in-warp; writes hs2[p], reds[p] ----
        {
            float vA0 = d[0] + d2[0], vA1 = d[1] + d2[1];
            float vB0 = d[2] + d2[2], vB1 = d[3] + d2[3];
            float tA0 = ftanh(0.5f*vA0), tA1 = ftanh(0.5f*vA1);
            float tB0 = ftanh(sB*vB0),   tB1 = ftanh(sB*vB1);
            float uA0 = fmaf(0.5f,tA0,0.5f), uA1 = fmaf(0.5f,tA1,0.5f);
            float uB0 = fmaf(pBm,tB0,pBa),   uB1 = fmaf(pBm,tB1,pBa);
            float prod0 = uA0*uB0, prod1 = uA1*uB1;
            float r1 = __shfl_xor_sync(0xFFFFFFFFu, low ? prod1 : uA0, 16);
            float r2 = __shfl_xor_sync(0xFFFFFFFFu, low ? 0.f   : uB0, 16);
            float my_sf = low ? r1 : uA1;
            float my_pr = low ? prod0 : r1;
            float cn = fmaf(my_sf, c2, my_pr); c2 = cn;
            float tcn = ftanh(cn);
            float my_so = low ? r2 : uB1;
            float h = my_so * tcn;
            *(__half*)((char*)&hs2[p][bmy][0] + hoff) = __float2half_rn(h);
            float v = wlj * h;
            v += __shfl_xor_sync(0xFFFFFFFFu, v, 4);
            v += __shfl_xor_sync(0xFFFFFFFFu, v, 8);
            if (red_lane) reds[p][w * 8 + bmy] = v;
        }

        // ---- act1(t+1): MMA1 results long since ready ----
        if (has_next) {
            float vA0 = e[0] + e2[0], vA1 = e[1] + e2[1];
            float vB0 = e[2] + e2[2], vB1 = e[3] + e2[3];
            float tA0 = ftanh(0.5f*vA0), tA1 = ftanh(0.5f*vA1);
            float tB0 = ftanh(sB*vB0),   tB1 = ftanh(sB*vB1);
            float uA0 = fmaf(0.5f,tA0,0.5f), uA1 = fmaf(0.5f,tA1,0.5f);
            float uB0 = fmaf(pBm,tB0,pBa),   uB1 = fmaf(pBm,tB1,pBa);
            float prod0 = uA0*uB0, prod1 = uA1*uB1;
            float r1 = __shfl_xor_sync(0xFFFFFFFFu, low ? prod1 : uA0, 16);
            float r2 = __shfl_xor_sync(0xFFFFFFFFu, low ? 0.f   : uB0, 16);
            float my_sf = low ? r1 : uA1;
            float my_pr = low ? prod0 : r1;
            float cn = fmaf(my_sf, c1, my_pr); c1 = cn;
            float tcn = ftanh(cn);
            float my_so = low ? r2 : uB1;
            float h = my_so * tcn;
            *(__half*)((char*)&hs1[pn][bmy][0] + hoff) = __float2half_rn(h);
        }
        __syncthreads();
    }

    // ---- finalize out(SEQ-1) ----
    if (tid < NB) {
        float s = 0.f;
        #pragma unroll
        for (int ww = 0; ww < 16; ww++) s += reds[(SEQ - 1) & 1][ww * 8 + tid];
        out[(b0 + tid) * SEQ + (SEQ - 1)] = s + blin;
    }
}

extern "C" void kernel_launch(void* const* d_in, const int* in_sizes, int n_in,
                              void* d_out, int out_size) {
    (void)in_sizes; (void)n_in; (void)out_size;
    const float* input = (const float*)d_in[0];
    const float* W_ih1 = (const float*)d_in[1];
    const float* W_hh1 = (const float*)d_in[2];
    const float* b_ih1 = (const float*)d_in[3];
    const float* b_hh1 = (const float*)d_in[4];
    const float* W_ih2 = (const float*)d_in[5];
    const float* W_hh2 = (const float*)d_in[6];
    const float* b_ih2 = (const float*)d_in[7];
    const float* b_hh2 = (const float*)d_in[8];
    const float* W_lin = (const float*)d_in[9];
    const float* b_lin = (const float*)d_in[10];
    float* out = (float*)d_out;

    lstm_kernel<<<NCTA, TPB>>>(input, W_ih1, W_hh1, b_ih1, b_hh1,
                               W_ih2, W_hh2, b_ih2, b_hh2,
                               W_lin, b_lin, out);
}